// round 3
// baseline (speedup 1.0000x reference)
#include <cuda_runtime.h>

#define NL   16
#define CC   128
#define EE   10
#define P3C  23
#define P2C  4
#define P1C  1
#define MAXN 4096
#define MB   16

// Precomputed tables (per-launch, deterministic). __device__ globals are the
// sanctioned scratch mechanism (no runtime allocation).
__device__ float g_V[EE * CC * NL * NL * NL];   // [e][c][i][ab] : 21 MB
__device__ float g_U2w[EE * CC * NL * NL];      // [e][c][ab]
__device__ float g_U1w[EE * CC * NL];           // [e][c][a]
__device__ int   g_bins[EE * MAXN];             // atom indices grouped by type
__device__ int   g_counts[EE];

// ---------------------------------------------------------------------------
// Kernel A: V[e,c,i,ab] = sum_k U3[a,b,i,k] * W3[e,k,c]
// grid (NL, EE), 256 threads (tid = ab). ~120M FMA total, trivial.
// ---------------------------------------------------------------------------
__global__ void precompute_V(const float* __restrict__ U3,
                             const float* __restrict__ W3) {
    const int i   = blockIdx.x;   // 0..15
    const int e   = blockIdx.y;   // 0..9
    const int tid = threadIdx.x;  // ab = a*16+b

    __shared__ float W3s[P3C * CC];
    for (int idx = tid; idx < P3C * CC; idx += 256)
        W3s[idx] = W3[e * P3C * CC + idx];

    float u3r[P3C];
#pragma unroll
    for (int k = 0; k < P3C; k++)
        u3r[k] = U3[(tid * NL + i) * P3C + k];   // U3[a][b][i][k]
    __syncthreads();

    for (int c = 0; c < CC; c++) {
        float acc = 0.f;
#pragma unroll
        for (int k = 0; k < P3C; k++)
            acc += u3r[k] * W3s[k * CC + c];     // broadcast LDS
        g_V[(((size_t)e * CC + c) * NL + i) * (NL * NL) + tid] = acc; // coalesced
    }
}

// ---------------------------------------------------------------------------
// Kernel B: U2w[e,c,ab] = sum_k U2[a,b,k]*W2[e,k,c];
//           U1w[e,c,a]  = sum_k U1[a,k]*W1[e,k,c]
// ---------------------------------------------------------------------------
__global__ void precompute_U21(const float* __restrict__ U2,
                               const float* __restrict__ W2,
                               const float* __restrict__ U1,
                               const float* __restrict__ W1) {
    const int e   = blockIdx.x;
    const int tid = threadIdx.x;

    __shared__ float W2s[P2C * CC];
    __shared__ float W1s[P1C * CC];
    for (int idx = tid; idx < P2C * CC; idx += 256) W2s[idx] = W2[e * P2C * CC + idx];
    for (int idx = tid; idx < P1C * CC; idx += 256) W1s[idx] = W1[e * P1C * CC + idx];

    float u2r[P2C];
#pragma unroll
    for (int k = 0; k < P2C; k++) u2r[k] = U2[tid * P2C + k];
    __syncthreads();

    for (int c = 0; c < CC; c++) {
        float acc = 0.f;
#pragma unroll
        for (int k = 0; k < P2C; k++) acc += u2r[k] * W2s[k * CC + c];
        g_U2w[((size_t)e * CC + c) * (NL * NL) + tid] = acc;
    }

    if (tid < NL) {
        float u1r[P1C];
#pragma unroll
        for (int k = 0; k < P1C; k++) u1r[k] = U1[tid * P1C + k];
        for (int c = 0; c < CC; c++) {
            float acc = 0.f;
#pragma unroll
            for (int k = 0; k < P1C; k++) acc += u1r[k] * W1s[k * CC + c];
            g_U1w[((size_t)e * CC + c) * NL + tid] = acc;
        }
    }
}

// ---------------------------------------------------------------------------
// Kernel C: deterministic binning of atoms by type.
// 1 block, EE warps. Warp e scans types (staged in smem) with ballot/popc.
// ---------------------------------------------------------------------------
__global__ void bin_atoms(const int* __restrict__ atom_types, int N) {
    __shared__ int ts[MAXN];
    for (int idx = threadIdx.x; idx < N; idx += blockDim.x)
        ts[idx] = atom_types[idx];
    __syncthreads();

    const int e    = threadIdx.x >> 5;
    const int lane = threadIdx.x & 31;
    if (e < EE) {
        int count = 0;
        for (int base = 0; base < N; base += 32) {
            int idx = base + lane;
            int t   = (idx < N) ? ts[idx] : -1;
            unsigned mask = __ballot_sync(0xffffffffu, t == e);
            if (t == e)
                g_bins[e * MAXN + count + __popc(mask & ((1u << lane) - 1u))] = idx;
            count += __popc(mask);
        }
        if (lane == 0) g_counts[e] = count;
    }
}

// ---------------------------------------------------------------------------
// Kernel D: main contraction. One CTA per (e, c). thread tid = ab, a=tid>>4,
// b=tid&15. V slice lives in 16 registers/thread; x row broadcast from smem.
//   c3[ab]  = u2w[ab] + sum_i v[i]*x[i]
//   c1[a]   = sum_b c3[ab]*x[b]            (shfl butterfly over 16 lanes)
//   out     = sum_a (c1[a]+u1w[a])*x[a]    (shfl_xor 16 + cross-warp smem red)
// ---------------------------------------------------------------------------
__global__ __launch_bounds__(256) void contract_kernel(const float* __restrict__ x,
                                                       float* __restrict__ out) {
    const int c    = blockIdx.x;
    const int e    = blockIdx.y;
    const int tid  = threadIdx.x;
    const int lane = tid & 31;
    const int w    = tid >> 5;
    const int b    = tid & 15;
    const int a    = tid >> 4;

    __shared__ __align__(16) float xs[MB][NL];
    __shared__ int   ns[MB];
    __shared__ float red[MB][8];

    const size_t ec = (size_t)e * CC + c;
    float v[NL];
    const float* Vp = g_V + ec * (NL * NL * NL);
#pragma unroll
    for (int i = 0; i < NL; i++)
        v[i] = Vp[i * (NL * NL) + tid];          // coalesced, once per CTA

    const float u2w  = g_U2w[ec * (NL * NL) + tid];
    const float u1wa = g_U1w[ec * NL + a];
    const int   count = g_counts[e];
    const int*  bins  = g_bins + e * MAXN;

    for (int base = 0; base < count; base += MB) {
        const int rem = min(MB, count - base);
        __syncthreads();   // protect xs/ns vs previous iteration's readers
        {
            const int m = tid >> 4, i = tid & 15;  // 256 threads stage 16 atoms
            if (m < rem) {
                const int n = bins[base + m];
                if (i == 0) ns[m] = n;
                xs[m][i] = x[(size_t)n * (NL * CC) + i * CC + c];
            }
        }
        __syncthreads();

        // Phase 1: c3 accumulators for all MB atoms (register V, LDS.128 x)
        float accs[MB];
#pragma unroll
        for (int m = 0; m < MB; m++) {
            float acc = u2w;
            const float4* xv = reinterpret_cast<const float4*>(xs[m]);
#pragma unroll
            for (int q = 0; q < 4; q++) {
                const float4 xq = xv[q];
                acc += v[4 * q + 0] * xq.x;
                acc += v[4 * q + 1] * xq.y;
                acc += v[4 * q + 2] * xq.z;
                acc += v[4 * q + 3] * xq.w;
            }
            accs[m] = acc;   // m >= rem computes stale-smem garbage, never stored
        }

        // Phase 2: reductions (independent across m -> pipelined shuffles)
#pragma unroll
        for (int m = 0; m < MB; m++) {
            float t = accs[m] * xs[m][b];
#pragma unroll
            for (int s = 1; s < 16; s <<= 1)
                t += __shfl_xor_sync(0xffffffffu, t, s);   // c1[a] on all 16 lanes
            float val = (t + u1wa) * xs[m][a];
            val += __shfl_xor_sync(0xffffffffu, val, 16);  // both a's of this warp
            if (lane == 0) red[m][w] = val;
        }
        __syncthreads();

        if (tid < rem) {
            float s = 0.f;
#pragma unroll
            for (int ww = 0; ww < 8; ww++) s += red[tid][ww];
            out[(size_t)ns[tid] * CC + c] = s;
        }
    }
}

// ---------------------------------------------------------------------------
extern "C" void kernel_launch(void* const* d_in, const int* in_sizes, int n_in,
                              void* d_out, int out_size) {
    const float* x  = (const float*)d_in[0];
    const int*   at = (const int*)d_in[1];
    const float* U3 = (const float*)d_in[2];
    const float* U2 = (const float*)d_in[3];
    const float* U1 = (const float*)d_in[4];
    const float* W3 = (const float*)d_in[5];
    const float* W2 = (const float*)d_in[6];
    const float* W1 = (const float*)d_in[7];
    float* out = (float*)d_out;
    const int N = in_sizes[1];   // atom_types element count

    precompute_V<<<dim3(NL, EE), 256>>>(U3, W3);
    precompute_U21<<<EE, 256>>>(U2, W2, U1, W1);
    bin_atoms<<<1, EE * 32>>>(at, N);
    contract_kernel<<<dim3(CC, EE), 256>>>(x, out);
}

// round 4
// speedup vs baseline: 1.6098x; 1.6098x over previous
#include <cuda_runtime.h>

#define NL    16
#define CC    128
#define EE    10
#define P3C   23
#define P2C   4
#define P1C   1
#define MAXN  4096
#define MB    16
#define SPLIT 4
#define BLMAX (MAXN / SPLIT)

// Precomputed tables (per-launch, deterministic). __device__ globals are the
// sanctioned scratch mechanism.
__device__ float g_V[EE * CC * NL * NL * NL];   // [e][c][i][ab] : 21 MB
__device__ float g_U2w[EE * CC * NL * NL];      // [e][c][ab]
__device__ float g_U1w[EE * CC * NL];           // [e][c][a]
__device__ float g_xT[(size_t)CC * MAXN * NL];  // [c][n][i] : 32 MB
__device__ int   g_bins[EE * MAXN];
__device__ int   g_counts[EE];

// ---------------------------------------------------------------------------
// Kernel A: V[e,c,i,ab] = sum_k U3[a,b,i,k] * W3[e,k,c]
// ---------------------------------------------------------------------------
__global__ void precompute_V(const float* __restrict__ U3,
                             const float* __restrict__ W3) {
    const int i   = blockIdx.x;
    const int e   = blockIdx.y;
    const int tid = threadIdx.x;  // ab

    __shared__ float W3s[P3C * CC];
    for (int idx = tid; idx < P3C * CC; idx += 256)
        W3s[idx] = W3[e * P3C * CC + idx];

    float u3r[P3C];
#pragma unroll
    for (int k = 0; k < P3C; k++)
        u3r[k] = U3[(tid * NL + i) * P3C + k];
    __syncthreads();

    for (int c = 0; c < CC; c++) {
        float acc = 0.f;
#pragma unroll
        for (int k = 0; k < P3C; k++)
            acc += u3r[k] * W3s[k * CC + c];
        g_V[(((size_t)e * CC + c) * NL + i) * (NL * NL) + tid] = acc;
    }
}

// ---------------------------------------------------------------------------
// Kernel B (combined): blocks 0..EE-1 do U2w/U1w; block EE bins atoms.
// 320 threads per block.
// ---------------------------------------------------------------------------
__global__ void setup_kernel(const float* __restrict__ U2,
                             const float* __restrict__ W2,
                             const float* __restrict__ U1,
                             const float* __restrict__ W1,
                             const int* __restrict__ atom_types, int N) {
    __shared__ float W2s[P2C * CC];
    __shared__ float W1s[P1C * CC];
    __shared__ int   ts[MAXN];

    const int bx  = blockIdx.x;
    const int tid = threadIdx.x;

    if (bx < EE) {
        const int e = bx;
        for (int idx = tid; idx < P2C * CC; idx += blockDim.x) W2s[idx] = W2[e * P2C * CC + idx];
        for (int idx = tid; idx < P1C * CC; idx += blockDim.x) W1s[idx] = W1[e * P1C * CC + idx];
        float u2r[P2C];
        if (tid < 256) {
#pragma unroll
            for (int k = 0; k < P2C; k++) u2r[k] = U2[tid * P2C + k];
        }
        __syncthreads();
        if (tid < 256) {
            for (int c = 0; c < CC; c++) {
                float acc = 0.f;
#pragma unroll
                for (int k = 0; k < P2C; k++) acc += u2r[k] * W2s[k * CC + c];
                g_U2w[((size_t)e * CC + c) * (NL * NL) + tid] = acc;
            }
            if (tid < NL) {
                float u1r[P1C];
#pragma unroll
                for (int k = 0; k < P1C; k++) u1r[k] = U1[tid * P1C + k];
                for (int c = 0; c < CC; c++) {
                    float acc = 0.f;
#pragma unroll
                    for (int k = 0; k < P1C; k++) acc += u1r[k] * W1s[k * CC + c];
                    g_U1w[((size_t)e * CC + c) * NL + tid] = acc;
                }
            }
        }
    } else {
        for (int idx = tid; idx < N; idx += blockDim.x) ts[idx] = atom_types[idx];
        __syncthreads();
        const int e    = tid >> 5;
        const int lane = tid & 31;
        if (e < EE) {
            int count = 0;
            for (int base = 0; base < N; base += 32) {
                int idx = base + lane;
                int t   = (idx < N) ? ts[idx] : -1;
                unsigned mask = __ballot_sync(0xffffffffu, t == e);
                if (t == e)
                    g_bins[e * MAXN + count + __popc(mask & ((1u << lane) - 1u))] = idx;
                count += __popc(mask);
            }
            if (lane == 0) g_counts[e] = count;
        }
    }
}

// ---------------------------------------------------------------------------
// Kernel C: transpose x[n][i][c] -> xT[c][n][i] for coalesced tile gathers.
// ---------------------------------------------------------------------------
__global__ void transpose_x(const float* __restrict__ x, int N) {
    __shared__ float tile[NL * (CC + 1)];
    const int n = blockIdx.x;
    for (int idx = threadIdx.x; idx < NL * CC; idx += 256) {
        int i = idx / CC, c = idx % CC;
        tile[i * (CC + 1) + c] = x[(size_t)n * NL * CC + idx];
    }
    __syncthreads();
    for (int idx = threadIdx.x; idx < NL * CC; idx += 256) {
        int c = idx >> 4, i = idx & 15;
        g_xT[((size_t)c * MAXN + n) * NL + i] = tile[i * (CC + 1) + c];
    }
}

// ---------------------------------------------------------------------------
// Kernel D: main contraction. CTA = (c, e, z-split). thread = ab.
// val[ab] = (u2w[ab] + sum_i V[i,ab]*x_i) * x_b * x_a  (+ u1w[a]*x_a on b==0)
// out[n,c] = sum_ab val  — merged-butterfly reduction: 15 SHFL / 16 atoms.
// ---------------------------------------------------------------------------
__global__ __launch_bounds__(256) void contract_kernel(float* __restrict__ out) {
    const int c    = blockIdx.x;
    const int e    = blockIdx.y;
    const int z    = blockIdx.z;
    const int tid  = threadIdx.x;
    const int lane = tid & 31;
    const int w    = tid >> 5;
    const int b    = tid & 15;
    const int a    = tid >> 4;
    const int m    = tid >> 4;   // staging row
    const int i    = tid & 15;   // staging col

    __shared__ __align__(16) float xs[MB][NL];
    __shared__ float red[MB][9];
    __shared__ int   bl[BLMAX];

    const int count  = g_counts[e];
    const int ntiles = (count + MB - 1) / MB;
    const int tpc    = (ntiles + SPLIT - 1) / SPLIT;
    const int begin  = min(count, z * tpc * MB);
    const int end    = min(count, begin + tpc * MB);
    const int nloc   = end - begin;

    const size_t ec = (size_t)e * CC + c;
    float v[NL];
    const float* Vp = g_V + ec * (NL * NL * NL);
#pragma unroll
    for (int q = 0; q < NL; q++) v[q] = Vp[q * (NL * NL) + tid];
    const float u2w  = g_U2w[ec * (NL * NL) + tid];
    const float u1wa = g_U1w[ec * NL + a];

    const int* bins = g_bins + e * MAXN + begin;
    for (int idx = tid; idx < nloc; idx += 256) bl[idx] = bins[idx];
    __syncthreads();
    if (nloc <= 0) return;

    const float* xTc = g_xT + (size_t)c * MAXN * NL;

    // prefetch tile 0 (coalesced: 16 consecutive floats per atom)
    float xr = 0.f;
    if (m < nloc) xr = xTc[(size_t)bl[m] * NL + i];

    const int mlane = ((lane >> 4) & 1) | (((lane >> 3) & 1) << 1)
                    | (((lane >> 2) & 1) << 2) | (((lane >> 1) & 1) << 3);

    for (int t0 = 0; t0 < nloc; t0 += MB) {
        const int rem = min(MB, nloc - t0);
        if (m < rem) xs[m][i] = xr;
        __syncthreads();

        // prefetch next tile into registers (hidden under compute)
        float xrn = 0.f;
        {
            const int nxt = t0 + MB + m;
            if (nxt < nloc) xrn = xTc[(size_t)bl[nxt] * NL + i];
        }

        // fused phase1 (register-V FMAs) + stage-1 merge
        float m0[8];
#pragma unroll
        for (int k = 0; k < 8; k++) {
            float pv[2];
#pragma unroll
            for (int h = 0; h < 2; h++) {
                const int mm = 2 * k + h;
                const float4* xq = reinterpret_cast<const float4*>(xs[mm]);
                float4 x0 = xq[0], x1 = xq[1], x2 = xq[2], x3 = xq[3];
                float acc = u2w;
                acc = fmaf(v[0],  x0.x, acc); acc = fmaf(v[1],  x0.y, acc);
                acc = fmaf(v[2],  x0.z, acc); acc = fmaf(v[3],  x0.w, acc);
                acc = fmaf(v[4],  x1.x, acc); acc = fmaf(v[5],  x1.y, acc);
                acc = fmaf(v[6],  x1.z, acc); acc = fmaf(v[7],  x1.w, acc);
                acc = fmaf(v[8],  x2.x, acc); acc = fmaf(v[9],  x2.y, acc);
                acc = fmaf(v[10], x2.z, acc); acc = fmaf(v[11], x2.w, acc);
                acc = fmaf(v[12], x3.x, acc); acc = fmaf(v[13], x3.y, acc);
                acc = fmaf(v[14], x3.z, acc); acc = fmaf(v[15], x3.w, acc);
                float t1 = acc * xs[mm][b];
                if (b == 0) t1 += u1wa;
                pv[h] = t1 * xs[mm][a];
            }
            const bool up = (lane & 16);
            float mine = up ? pv[1] : pv[0];
            float oth  = up ? pv[0] : pv[1];
            m0[k] = mine + __shfl_xor_sync(0xffffffffu, oth, 16);
        }
        float m1[4];
#pragma unroll
        for (int k = 0; k < 4; k++) {
            const bool up = (lane & 8);
            float mine = up ? m0[2 * k + 1] : m0[2 * k];
            float oth  = up ? m0[2 * k]     : m0[2 * k + 1];
            m1[k] = mine + __shfl_xor_sync(0xffffffffu, oth, 8);
        }
        float m2[2];
#pragma unroll
        for (int k = 0; k < 2; k++) {
            const bool up = (lane & 4);
            float mine = up ? m1[2 * k + 1] : m1[2 * k];
            float oth  = up ? m1[2 * k]     : m1[2 * k + 1];
            m2[k] = mine + __shfl_xor_sync(0xffffffffu, oth, 4);
        }
        {
            const bool up = (lane & 2);
            float mine = up ? m2[1] : m2[0];
            float oth  = up ? m2[0] : m2[1];
            float m3 = mine + __shfl_xor_sync(0xffffffffu, oth, 2);
            m3 += __shfl_xor_sync(0xffffffffu, m3, 1);
            if ((lane & 1) == 0) red[mlane][w] = m3;
        }
        __syncthreads();

        if (tid < rem) {
            float s = red[tid][0] + red[tid][1] + red[tid][2] + red[tid][3]
                    + red[tid][4] + red[tid][5] + red[tid][6] + red[tid][7];
            out[(size_t)bl[t0 + tid] * CC + c] = s;
        }
        __syncthreads();
        xr = xrn;
    }
}

// ---------------------------------------------------------------------------
extern "C" void kernel_launch(void* const* d_in, const int* in_sizes, int n_in,
                              void* d_out, int out_size) {
    const float* x  = (const float*)d_in[0];
    const int*   at = (const int*)d_in[1];
    const float* U3 = (const float*)d_in[2];
    const float* U2 = (const float*)d_in[3];
    const float* U1 = (const float*)d_in[4];
    const float* W3 = (const float*)d_in[5];
    const float* W2 = (const float*)d_in[6];
    const float* W1 = (const float*)d_in[7];
    float* out = (float*)d_out;
    const int N = in_sizes[1];

    precompute_V<<<dim3(NL, EE), 256>>>(U3, W3);
    setup_kernel<<<EE + 1, 320>>>(U2, W2, U1, W1, at, N);
    transpose_x<<<N, 256>>>(x, N);
    contract_kernel<<<dim3(CC, EE, SPLIT), 256>>>(out);
}

// round 5
// speedup vs baseline: 3.3531x; 2.0829x over previous
#include <cuda_runtime.h>

#define NL    16
#define CC    128
#define EE    10
#define P3C   23
#define P2C   4
#define MAXN  4096
#define MB    16
#define SPLIT 4
#define BLMAX (MAXN / SPLIT)
#define NPOS  1120     // 32*(16+9+6+3+1) padded sym-coeff positions per (e,c)
#define NSLOT 160      // 5 chunks * 32 lanes
#define NACT  136      // active pairs a<=b

// __device__ globals = sanctioned scratch.
__device__ float g_S[(size_t)EE * CC * NPOS];   // symmetrized cubic coeffs  (5.7 MB)
__device__ float g_Q[EE * CC * NSLOT];          // symmetrized quadratic coeffs
__device__ float g_L[EE * CC * NL];             // linear coeffs
__device__ float g_U3S[NPOS * P3C];             // symmetrized U3 (shared over e,c)
__device__ float g_xT[(size_t)CC * MAXN * NL];  // x transposed [c][n][i]
__device__ int   g_bins[EE * MAXN];
__device__ int   g_counts[EE];

// slot s (sorted-by-length pair list: a=15..0, b=a..15) -> (a,b)
__device__ __forceinline__ void slot_ab(int s, int& a, int& b) {
    a = 0; b = 0;
    int off = 0;
#pragma unroll
    for (int aa = 15; aa >= 0; aa--) {
        int cnt = 16 - aa;
        if (s >= off && s < off + cnt) { a = aa; b = aa + (s - off); }
        off += cnt;
    }
}

__device__ __forceinline__ float u3at(const float* U3, int d0, int d1, int d2, int k) {
    return U3[((d0 * NL + d1) * NL + d2) * P3C + k];
}

// ---------------------------------------------------------------------------
// Kernel 1: symmetrize U3 into padded chunk layout.
// position p -> (chunk, j=inner i, lane); slot = chunk*32+lane.
// S'[{i<=a<=b}][k] = sum_{sigma in S3} U3[sigma(i,a,b)][k] / r  (r = |stabilizer|)
// ---------------------------------------------------------------------------
__global__ void sym_u3_kernel(const float* __restrict__ U3) {
    const int idx = blockIdx.x * 256 + threadIdx.x;
    if (idx >= NPOS * P3C) return;
    const int p = idx / P3C;
    const int k = idx - p * P3C;

    int base;
    int ch;
    if      (p < 512)  { ch = 0; base = 0;    }
    else if (p < 800)  { ch = 1; base = 512;  }
    else if (p < 992)  { ch = 2; base = 800;  }
    else if (p < 1088) { ch = 3; base = 992;  }
    else               { ch = 4; base = 1088; }
    const int rel = p - base;
    const int j = rel >> 5;          // inner index i
    const int l = rel & 31;
    const int s = ch * 32 + l;

    float val = 0.f;
    if (s < NACT) {
        int a, b; slot_ab(s, a, b);
        const int i = j;
        if (i <= a) {
            float sum = u3at(U3, i, a, b, k) + u3at(U3, i, b, a, k)
                      + u3at(U3, a, i, b, k) + u3at(U3, a, b, i, k)
                      + u3at(U3, b, i, a, k) + u3at(U3, b, a, i, k);
            float r = (i == a && a == b) ? 6.f : ((i == a || a == b) ? 2.f : 1.f);
            val = sum / r;
        }
    }
    g_U3S[idx] = val;   // idx == p*P3C + k
}

// ---------------------------------------------------------------------------
// Kernel 2: contract U3S/U2/U1 with per-type weights -> g_S, g_Q, g_L.
// block = (c-tile of 8, e)
// ---------------------------------------------------------------------------
__global__ void precompute_S(const float* __restrict__ W3,
                             const float* __restrict__ U2,
                             const float* __restrict__ W2,
                             const float* __restrict__ U1,
                             const float* __restrict__ W1) {
    const int c0  = blockIdx.x * 8;
    const int e   = blockIdx.y;
    const int tid = threadIdx.x;

    __shared__ float W3s[P3C * 8];
    __shared__ float W2s[P2C * 8];
    __shared__ float W1s[8];
    for (int idx = tid; idx < P3C * 8; idx += 256) {
        int k = idx >> 3, cl = idx & 7;
        W3s[idx] = W3[(e * P3C + k) * CC + c0 + cl];
    }
    if (tid < P2C * 8) {
        int k = tid >> 3, cl = tid & 7;
        W2s[tid] = W2[(e * P2C + k) * CC + c0 + cl];
    }
    if (tid < 8) W1s[tid] = W1[e * CC + c0 + tid];
    __syncthreads();

    for (int p = tid; p < NPOS; p += 256) {
        float u[P3C];
#pragma unroll
        for (int k = 0; k < P3C; k++) u[k] = g_U3S[p * P3C + k];
#pragma unroll
        for (int cl = 0; cl < 8; cl++) {
            float acc = 0.f;
#pragma unroll
            for (int k = 0; k < P3C; k++) acc += u[k] * W3s[k * 8 + cl];
            g_S[((size_t)(e * CC + c0 + cl)) * NPOS + p] = acc;
        }
    }

    if (tid < NSLOT) {
        const int s = tid;
        int a = 0, b = 0;
        const bool act = (s < NACT);
        if (act) slot_ab(s, a, b);
#pragma unroll
        for (int cl = 0; cl < 8; cl++) {
            float q = 0.f;
            if (act) {
                float Bab = 0.f, Bba = 0.f;
#pragma unroll
                for (int k = 0; k < P2C; k++) {
                    Bab += U2[(a * NL + b) * P2C + k] * W2s[k * 8 + cl];
                    Bba += U2[(b * NL + a) * P2C + k] * W2s[k * 8 + cl];
                }
                q = (a == b) ? Bab : (Bab + Bba);
            }
            g_Q[(size_t)(e * CC + c0 + cl) * NSLOT + s] = q;
        }
    }
    if (tid < NL) {
#pragma unroll
        for (int cl = 0; cl < 8; cl++)
            g_L[(size_t)(e * CC + c0 + cl) * NL + tid] = U1[tid] * W1s[cl];
    }
}

// ---------------------------------------------------------------------------
// Kernel 3: deterministic binning (unchanged from R3).
// ---------------------------------------------------------------------------
__global__ void bin_atoms(const int* __restrict__ atom_types, int N) {
    __shared__ int ts[MAXN];
    for (int idx = threadIdx.x; idx < N; idx += blockDim.x) ts[idx] = atom_types[idx];
    __syncthreads();
    const int e = threadIdx.x >> 5, lane = threadIdx.x & 31;
    if (e < EE) {
        int count = 0;
        for (int base = 0; base < N; base += 32) {
            int idx = base + lane;
            int t = (idx < N) ? ts[idx] : -1;
            unsigned mask = __ballot_sync(0xffffffffu, t == e);
            if (t == e)
                g_bins[e * MAXN + count + __popc(mask & ((1u << lane) - 1u))] = idx;
            count += __popc(mask);
        }
        if (lane == 0) g_counts[e] = count;
    }
}

// ---------------------------------------------------------------------------
// Kernel 4: transpose x (unchanged from R4).
// ---------------------------------------------------------------------------
__global__ void transpose_x(const float* __restrict__ x, int N) {
    __shared__ float tile[NL * (CC + 1)];
    const int n = blockIdx.x;
    for (int idx = threadIdx.x; idx < NL * CC; idx += 256) {
        int i = idx / CC, c = idx % CC;
        tile[i * (CC + 1) + c] = x[(size_t)n * NL * CC + idx];
    }
    __syncthreads();
    for (int idx = threadIdx.x; idx < NL * CC; idx += 256) {
        int c = idx >> 4, i = idx & 15;
        g_xT[((size_t)c * MAXN + n) * NL + i] = tile[i * (CC + 1) + c];
    }
}

// ---------------------------------------------------------------------------
// Kernel 5: main contraction, symmetric monomial form. 64 threads = 2 warps.
//   warp0: chunks 0 (len16) + 3 (len3);  warp1: chunks 1 (9) + 2 (6) + 4 (1) + linear
//   out[n,c] = sum_slots (Q[slot] + sum_i S'[slot][i] x_i) * x_a * x_b + sum_a L_a x_a
// ---------------------------------------------------------------------------
__global__ __launch_bounds__(64) void contract_kernel(float* __restrict__ out) {
    const int c = blockIdx.x, e = blockIdx.y, z = blockIdx.z;
    const int t = threadIdx.x;
    const int w = t >> 5, lane = t & 31;

    __shared__ __align__(16) float xs[MB][NL];
    __shared__ float red[MB][2];
    __shared__ int bl[BLMAX];

    const int count  = g_counts[e];
    const int ntiles = (count + MB - 1) / MB;
    const int tpc    = (ntiles + SPLIT - 1) / SPLIT;
    const int begin  = min(count, z * tpc * MB);
    const int end    = min(count, begin + tpc * MB);
    const int nloc   = end - begin;

    const size_t ec = (size_t)e * CC + c;
    const float* Sp = g_S + ec * NPOS;
    const float* Qp = g_Q + ec * NSLOT;
    const float* Lp = g_L + ec * NL;

    float kk[19];
    float q0, q1, q2 = 0.f;
    int a0, b0, a1, b1, a2 = 0, b2 = 0;
    if (w == 0) {
#pragma unroll
        for (int j = 0; j < 16; j++) kk[j] = Sp[j * 32 + lane];          // chunk0
#pragma unroll
        for (int j = 0; j < 3; j++) kk[16 + j] = Sp[992 + j * 32 + lane]; // chunk3
        q0 = Qp[lane];
        q1 = Qp[96 + lane];
        slot_ab(lane, a0, b0);
        slot_ab(96 + lane, a1, b1);
    } else {
#pragma unroll
        for (int j = 0; j < 9; j++) kk[j] = Sp[512 + j * 32 + lane];      // chunk1
#pragma unroll
        for (int j = 0; j < 6; j++) kk[9 + j] = Sp[800 + j * 32 + lane];  // chunk2
        kk[15] = Sp[1088 + lane];                                          // chunk4
        kk[16] = (lane < NL) ? Lp[lane] : 0.f;                             // linear
        q0 = Qp[32 + lane];
        q1 = Qp[64 + lane];
        q2 = Qp[128 + lane];
        slot_ab(32 + lane, a0, b0);
        slot_ab(64 + lane, a1, b1);
        int s2 = 128 + lane;
        if (s2 < NACT) slot_ab(s2, a2, b2);   // else a2=b2=0, coeffs are zero
    }

    const int* bins = g_bins + e * MAXN + begin;
    for (int idx = t; idx < nloc; idx += 64) bl[idx] = bins[idx];
    __syncthreads();
    if (nloc <= 0) return;

    const float* xTc = g_xT + (size_t)c * MAXN * NL;

    const int satm = t >> 2;   // staged atom
    const int sq   = t & 3;    // staged quarter
    float4 xr = make_float4(0.f, 0.f, 0.f, 0.f);
    if (satm < nloc)
        xr = reinterpret_cast<const float4*>(xTc + (size_t)bl[satm] * NL)[sq];

    const int mlane = ((lane >> 4) & 1) | (((lane >> 3) & 1) << 1)
                    | (((lane >> 2) & 1) << 2) | (((lane >> 1) & 1) << 3);
    const int xlin = lane & 15;

    for (int t0 = 0; t0 < nloc; t0 += MB) {
        const int rem = min(MB, nloc - t0);
        if (satm < rem)
            reinterpret_cast<float4*>(xs[satm])[sq] = xr;
        __syncthreads();

        // prefetch next tile
        float4 xrn = make_float4(0.f, 0.f, 0.f, 0.f);
        {
            const int nxt = t0 + MB + satm;
            if (nxt < nloc)
                xrn = reinterpret_cast<const float4*>(xTc + (size_t)bl[nxt] * NL)[sq];
        }

        float val[MB];
#pragma unroll
        for (int mm = 0; mm < MB; mm++) {
            const float4* xv = reinterpret_cast<const float4*>(xs[mm]);
            const float4 X0 = xv[0], X1 = xv[1], X2 = xv[2], X3 = xv[3];
            float v;
            if (w == 0) {
                float G0 = q0;
                G0 = fmaf(kk[0],  X0.x, G0); G0 = fmaf(kk[1],  X0.y, G0);
                G0 = fmaf(kk[2],  X0.z, G0); G0 = fmaf(kk[3],  X0.w, G0);
                G0 = fmaf(kk[4],  X1.x, G0); G0 = fmaf(kk[5],  X1.y, G0);
                G0 = fmaf(kk[6],  X1.z, G0); G0 = fmaf(kk[7],  X1.w, G0);
                G0 = fmaf(kk[8],  X2.x, G0); G0 = fmaf(kk[9],  X2.y, G0);
                G0 = fmaf(kk[10], X2.z, G0); G0 = fmaf(kk[11], X2.w, G0);
                G0 = fmaf(kk[12], X3.x, G0); G0 = fmaf(kk[13], X3.y, G0);
                G0 = fmaf(kk[14], X3.z, G0); G0 = fmaf(kk[15], X3.w, G0);
                float G1 = q1;
                G1 = fmaf(kk[16], X0.x, G1); G1 = fmaf(kk[17], X0.y, G1);
                G1 = fmaf(kk[18], X0.z, G1);
                v = G0 * xs[mm][a0] * xs[mm][b0]
                  + G1 * xs[mm][a1] * xs[mm][b1];
            } else {
                float G0 = q0;
                G0 = fmaf(kk[0], X0.x, G0); G0 = fmaf(kk[1], X0.y, G0);
                G0 = fmaf(kk[2], X0.z, G0); G0 = fmaf(kk[3], X0.w, G0);
                G0 = fmaf(kk[4], X1.x, G0); G0 = fmaf(kk[5], X1.y, G0);
                G0 = fmaf(kk[6], X1.z, G0); G0 = fmaf(kk[7], X1.w, G0);
                G0 = fmaf(kk[8], X2.x, G0);
                float G1 = q1;
                G1 = fmaf(kk[9],  X0.x, G1); G1 = fmaf(kk[10], X0.y, G1);
                G1 = fmaf(kk[11], X0.z, G1); G1 = fmaf(kk[12], X0.w, G1);
                G1 = fmaf(kk[13], X1.x, G1); G1 = fmaf(kk[14], X1.y, G1);
                float G2 = fmaf(kk[15], X0.x, q2);
                v = G0 * xs[mm][a0] * xs[mm][b0]
                  + G1 * xs[mm][a1] * xs[mm][b1]
                  + G2 * xs[mm][a2] * xs[mm][b2]
                  + kk[16] * xs[mm][xlin];
            }
            val[mm] = v;
        }

        // merged butterfly: 16 atom-sums over 32 lanes, 16 SHFL (R3-validated)
        float m0[8];
#pragma unroll
        for (int k = 0; k < 8; k++) {
            const bool up = (lane & 16);
            float mine = up ? val[2 * k + 1] : val[2 * k];
            float oth  = up ? val[2 * k]     : val[2 * k + 1];
            m0[k] = mine + __shfl_xor_sync(0xffffffffu, oth, 16);
        }
        float m1[4];
#pragma unroll
        for (int k = 0; k < 4; k++) {
            const bool up = (lane & 8);
            float mine = up ? m0[2 * k + 1] : m0[2 * k];
            float oth  = up ? m0[2 * k]     : m0[2 * k + 1];
            m1[k] = mine + __shfl_xor_sync(0xffffffffu, oth, 8);
        }
        float m2[2];
#pragma unroll
        for (int k = 0; k < 2; k++) {
            const bool up = (lane & 4);
            float mine = up ? m1[2 * k + 1] : m1[2 * k];
            float oth  = up ? m1[2 * k]     : m1[2 * k + 1];
            m2[k] = mine + __shfl_xor_sync(0xffffffffu, oth, 4);
        }
        {
            const bool up = (lane & 2);
            float mine = up ? m2[1] : m2[0];
            float oth  = up ? m2[0] : m2[1];
            float m3 = mine + __shfl_xor_sync(0xffffffffu, oth, 2);
            m3 += __shfl_xor_sync(0xffffffffu, m3, 1);
            if ((lane & 1) == 0) red[mlane][w] = m3;
        }
        __syncthreads();

        if (t < rem)
            out[(size_t)bl[t0 + t] * CC + c] = red[t][0] + red[t][1];

        xr = xrn;
        __syncthreads();
    }
}

// ---------------------------------------------------------------------------
extern "C" void kernel_launch(void* const* d_in, const int* in_sizes, int n_in,
                              void* d_out, int out_size) {
    const float* x  = (const float*)d_in[0];
    const int*   at = (const int*)d_in[1];
    const float* U3 = (const float*)d_in[2];
    const float* U2 = (const float*)d_in[3];
    const float* U1 = (const float*)d_in[4];
    const float* W3 = (const float*)d_in[5];
    const float* W2 = (const float*)d_in[6];
    const float* W1 = (const float*)d_in[7];
    float* out = (float*)d_out;
    const int N = in_sizes[1];

    sym_u3_kernel<<<(NPOS * P3C + 255) / 256, 256>>>(U3);
    precompute_S<<<dim3(CC / 8, EE), 256>>>(W3, U2, W2, U1, W1);
    bin_atoms<<<1, EE * 32>>>(at, N);
    transpose_x<<<N, 256>>>(x, N);
    contract_kernel<<<dim3(CC, EE, SPLIT), 64>>>(out);
}